// round 14
// baseline (speedup 1.0000x reference)
#include <cuda_runtime.h>

#define BATCH 128
#define SEQ   2000
#define EMB   50
#define VOCAB 1000000
#define SPLIT 8
#define CHUNK (SEQ / SPLIT)      // 250 tokens per block
#define WARPS 8
#define THREADS (WARPS * 32)
#define HALF_EMB 25              // 25 float2 per row
#define MLP 8                    // gather streams in flight per lane
#define NBATCH (CHUNK / MLP)     // 31 full 8-token batches per block

// Cross-block accumulators (zero-init at module load; each launch leaves them
// zeroed again -> graph-replay safe, no zeroing pass).
__device__ float g_accum[BATCH][2];
__device__ int   g_cnt[BATCH];

__global__ __launch_bounds__(THREADS) void fused_kernel(
    const int* __restrict__ t32, const float* __restrict__ emb,
    const float* __restrict__ W, const float* __restrict__ bias,
    float* __restrict__ out)
{
    const int b     = blockIdx.y;
    const int chunk = blockIdx.x;
    const int warp  = threadIdx.x >> 5;
    const int lane  = threadIdx.x & 31;

    // ---- inline dtype detect (warp 0: 1 parallel load + ballot) ----
    // int64 indices in [-1, 1e6): every odd 32-bit word is 0 or -1.
    __shared__ int s_is64;
    if (threadIdx.x < 32) {
        const unsigned int hi =
            reinterpret_cast<const unsigned int*>(t32)[2 * lane + 1];
        const bool ok = (hi == 0u) || (hi == 0xFFFFFFFFu);
        const unsigned m = __ballot_sync(0xFFFFFFFFu, ok);
        if (lane == 0) s_is64 = (m == 0xFFFFFFFFu) ? 1 : 0;
    }
    __syncthreads();
    const int stride = s_is64 ? 2 : 1;   // 32-bit-word stride per index

    // ---- stage this block's 250 indices into smem (one coalesced pass) ----
    __shared__ int s_idx[CHUNK];
    {
        const int* tchunk = t32 +
            ((long long)b * SEQ + (long long)chunk * CHUNK) * stride;
        for (int i = threadIdx.x; i < CHUNK; i += THREADS)
            s_idx[i] = tchunk[i * stride];
    }
    __syncthreads();

    const bool active = (lane < HALF_EMB);
    const int  lp     = active ? lane : 0;   // inactive lanes broadcast slot 0
    const float2* __restrict__ emb2 = reinterpret_cast<const float2*>(emb);

    float2 accA = make_float2(0.f, 0.f);
    float2 accB = make_float2(0.f, 0.f);

    // Full 8-token batches, round-robined across warps. Indices come from
    // smem (29 cyc) so the only global-latency chain is the 8 row gathers.
    for (int bat = warp; bat < NBATCH; bat += WARPS) {
        const int s0 = bat * MLP;
        int vb[MLP];
        #pragma unroll
        for (int i = 0; i < MLP; i++)
            vb[i] = s_idx[s0 + i];               // smem broadcast, cheap

        float2 t[MLP];
        #pragma unroll
        for (int i = 0; i < MLP; i++) {
            const int safe = ((unsigned)vb[i] < (unsigned)VOCAB) ? vb[i] : 0;
            t[i] = emb2[safe * HALF_EMB + lp];   // 8 independent gathers
        }

        #pragma unroll
        for (int i = 0; i < MLP; i++) {
            if (active && (unsigned)vb[i] < (unsigned)VOCAB) {
                if (i & 1) { accB.x += t[i].x; accB.y += t[i].y; }
                else       { accA.x += t[i].x; accA.y += t[i].y; }
            }
        }
    }
    // Remainder tokens (CHUNK - NBATCH*MLP = 2), strided across warps.
    for (int s = NBATCH * MLP + warp; s < CHUNK; s += WARPS) {
        const int v = s_idx[s];
        if (active && (unsigned)v < (unsigned)VOCAB) {
            const float2 e = emb2[v * HALF_EMB + lp];
            accA.x += e.x; accA.y += e.y;
        }
    }
    accA.x += accB.x;
    accA.y += accB.y;

    // Block reduction across the 8 warps (per embedding-pair slot j = lane).
    __shared__ float2 red[WARPS][HALF_EMB];
    if (active) red[warp][lane] = accA;
    __syncthreads();

    // Warp 0: fold 25 slots into the 2 output dot products, then the
    // cross-block epilogue via atomics (last block for this b finalizes).
    if (warp == 0) {
        float c0 = 0.f, c1 = 0.f;
        if (active) {
            const int j = lane;
            const float w00 = __ldg(&W[2 * j]);
            const float w01 = __ldg(&W[2 * j + 1]);
            const float w10 = __ldg(&W[EMB + 2 * j]);
            const float w11 = __ldg(&W[EMB + 2 * j + 1]);
            float2 sum = red[0][j];
            #pragma unroll
            for (int w = 1; w < WARPS; w++) {
                sum.x += red[w][j].x;
                sum.y += red[w][j].y;
            }
            c0 = sum.x * w00 + sum.y * w01;
            c1 = sum.x * w10 + sum.y * w11;
        }
        #pragma unroll
        for (int off = 16; off > 0; off >>= 1) {
            c0 += __shfl_down_sync(0xFFFFFFFFu, c0, off);
            c1 += __shfl_down_sync(0xFFFFFFFFu, c1, off);
        }

        if (lane == 0) {
            atomicAdd(&g_accum[b][0], c0);
            atomicAdd(&g_accum[b][1], c1);
            __threadfence();                       // release accum before count
            const int prev = atomicAdd(&g_cnt[b], 1);
            if (prev == SPLIT - 1) {               // last block for this b
                __threadfence();                   // acquire all accum adds
                const float s0 = g_accum[b][0];
                const float s1 = g_accum[b][1];
                const float scale = 1.0f / (float)BATCH;  // ref divides by len(t)
                out[2 * b + 0] = fmaxf(bias[0] + scale * s0, 0.0f);
                out[2 * b + 1] = fmaxf(bias[1] + scale * s1, 0.0f);
                // Reset for the next graph replay.
                g_accum[b][0] = 0.f;
                g_accum[b][1] = 0.f;
                __threadfence();
                g_cnt[b] = 0;
            }
        }
    }
}

extern "C" void kernel_launch(void* const* d_in, const int* in_sizes, int n_in,
                              void* d_out, int out_size)
{
    const int*   t32 = (const int*)d_in[0];        // int32 OR int64 [128, 2000]
    const float* emb = (const float*)d_in[1];      // f32 [1e6, 50]
    const float* W   = (const float*)d_in[2];      // f32 [2, 50]
    const float* bia = (const float*)d_in[3];      // f32 [2]
    float*       out = (float*)d_out;              // f32 [128, 2]

    dim3 grid(SPLIT, BATCH);                       // 1024 CTAs ~= 6.9/SM, 1 wave
    fused_kernel<<<grid, THREADS>>>(t32, emb, W, bia, out);
}

// round 15
// speedup vs baseline: 1.2281x; 1.2281x over previous
#include <cuda_runtime.h>

#define BATCH 128
#define SEQ   2000
#define EMB   50
#define VOCAB 1000000
#define SPLIT 5
#define CHUNK (SEQ / SPLIT)      // 400 tokens per block
#define WARPS 8
#define THREADS (WARPS * 32)
#define TPW (CHUNK / WARPS)      // 50 contiguous tokens per warp
#define HALF_EMB 25              // 25 float2 per row
#define MLP 16                   // gather streams in flight per lane

// Cross-block accumulators (zero-init at module load; each launch leaves them
// zeroed again -> graph-replay safe, no zeroing pass).
__device__ float g_accum[BATCH][2];
__device__ int   g_cnt[BATCH];

__global__ __launch_bounds__(THREADS) void fused_kernel(
    const int* __restrict__ t32, const float* __restrict__ emb,
    const float* __restrict__ W, const float* __restrict__ bias,
    float* __restrict__ out)
{
    const int b     = blockIdx.y;
    const int chunk = blockIdx.x;
    const int warp  = threadIdx.x >> 5;
    const int lane  = threadIdx.x & 31;

    // ---- inline dtype detect (warp 0: 1 parallel load + ballot) ----
    // int64 indices in [-1, 1e6): every odd 32-bit word is 0 or -1.
    __shared__ int s_is64;
    if (threadIdx.x < 32) {
        const unsigned int hi =
            reinterpret_cast<const unsigned int*>(t32)[2 * lane + 1];
        const bool ok = (hi == 0u) || (hi == 0xFFFFFFFFu);
        const unsigned m = __ballot_sync(0xFFFFFFFFu, ok);
        if (lane == 0) s_is64 = (m == 0xFFFFFFFFu) ? 1 : 0;
    }
    __syncthreads();
    const int stride = s_is64 ? 2 : 1;   // 32-bit-word stride per index

    // Per-warp contiguous token range.
    const int* trow = t32 +
        ((long long)b * SEQ + (long long)chunk * CHUNK + (long long)warp * TPW)
        * stride;

    // ---- preload all 50 warp indices with 2 coalesced lane loads ----
    const int o0 = lane;                                  // tokens 0..31
    int o1 = 32 + lane;                                   // tokens 32..49
    if (o1 >= TPW) o1 = TPW - 1;                          // clamp (in-bounds)
    const int idx0 = trow[o0 * stride];
    const int idx1 = trow[o1 * stride];

    const bool active = (lane < HALF_EMB);
    const int  lp     = active ? lane : 0;   // inactive lanes broadcast slot 0
    const float2* __restrict__ emb2 = reinterpret_cast<const float2*>(emb);

    float2 acc0 = make_float2(0.f, 0.f);
    float2 acc1 = make_float2(0.f, 0.f);
    float2 acc2 = make_float2(0.f, 0.f);
    float2 acc3 = make_float2(0.f, 0.f);

    // 3 batches of 16 tokens: indices come from registers via shfl, so the
    // only global-latency chain per batch is the 16 independent row gathers.
    #pragma unroll
    for (int bat = 0; bat < 3; bat++) {
        int vb[MLP];
        #pragma unroll
        for (int i = 0; i < MLP; i++) {
            const int src = (bat == 1) ? (16 + i) : i;
            const int reg = (bat == 2) ? idx1 : idx0;
            vb[i] = __shfl_sync(0xFFFFFFFFu, reg, src);
        }

        float2 t[MLP];
        #pragma unroll
        for (int i = 0; i < MLP; i++) {
            const int safe = ((unsigned)vb[i] < (unsigned)VOCAB) ? vb[i] : 0;
            t[i] = emb2[safe * HALF_EMB + lp];   // 16 independent gathers
        }

        #pragma unroll
        for (int i = 0; i < MLP; i++) {
            if (active && (unsigned)vb[i] < (unsigned)VOCAB) {
                switch (i & 3) {
                    case 0: acc0.x += t[i].x; acc0.y += t[i].y; break;
                    case 1: acc1.x += t[i].x; acc1.y += t[i].y; break;
                    case 2: acc2.x += t[i].x; acc2.y += t[i].y; break;
                    default: acc3.x += t[i].x; acc3.y += t[i].y; break;
                }
            }
        }
    }
    // Tail: tokens 48, 49 (idx1 lanes 16, 17).
    #pragma unroll
    for (int r = 0; r < TPW - 48; r++) {
        const int v = __shfl_sync(0xFFFFFFFFu, idx1, 16 + r);
        if (active && (unsigned)v < (unsigned)VOCAB) {
            const float2 e = emb2[v * HALF_EMB + lp];
            acc0.x += e.x; acc0.y += e.y;
        }
    }
    acc0.x += acc1.x + acc2.x + acc3.x;
    acc0.y += acc1.y + acc2.y + acc3.y;

    // Block reduction across the 8 warps (per embedding-pair slot j = lane).
    __shared__ float2 red[WARPS][HALF_EMB];
    if (active) red[warp][lane] = acc0;
    __syncthreads();

    // Warp 0: fold 25 slots into the 2 output dot products, then the
    // cross-block epilogue via atomics (last block for this b finalizes).
    if (warp == 0) {
        float c0 = 0.f, c1 = 0.f;
        if (active) {
            const int j = lane;
            const float w00 = __ldg(&W[2 * j]);
            const float w01 = __ldg(&W[2 * j + 1]);
            const float w10 = __ldg(&W[EMB + 2 * j]);
            const float w11 = __ldg(&W[EMB + 2 * j + 1]);
            float2 sum = red[0][j];
            #pragma unroll
            for (int w = 1; w < WARPS; w++) {
                sum.x += red[w][j].x;
                sum.y += red[w][j].y;
            }
            c0 = sum.x * w00 + sum.y * w01;
            c1 = sum.x * w10 + sum.y * w11;
        }
        #pragma unroll
        for (int off = 16; off > 0; off >>= 1) {
            c0 += __shfl_down_sync(0xFFFFFFFFu, c0, off);
            c1 += __shfl_down_sync(0xFFFFFFFFu, c1, off);
        }

        if (lane == 0) {
            atomicAdd(&g_accum[b][0], c0);
            atomicAdd(&g_accum[b][1], c1);
            __threadfence();                       // release accum before count
            const int prev = atomicAdd(&g_cnt[b], 1);
            if (prev == SPLIT - 1) {               // last block for this b
                __threadfence();                   // acquire all accum adds
                const float s0 = g_accum[b][0];
                const float s1 = g_accum[b][1];
                const float scale = 1.0f / (float)BATCH;  // ref divides by len(t)
                out[2 * b + 0] = fmaxf(bias[0] + scale * s0, 0.0f);
                out[2 * b + 1] = fmaxf(bias[1] + scale * s1, 0.0f);
                // Reset for the next graph replay.
                g_accum[b][0] = 0.f;
                g_accum[b][1] = 0.f;
                __threadfence();
                g_cnt[b] = 0;
            }
        }
    }
}

extern "C" void kernel_launch(void* const* d_in, const int* in_sizes, int n_in,
                              void* d_out, int out_size)
{
    const int*   t32 = (const int*)d_in[0];        // int32 OR int64 [128, 2000]
    const float* emb = (const float*)d_in[1];      // f32 [1e6, 50]
    const float* W   = (const float*)d_in[2];      // f32 [2, 50]
    const float* bia = (const float*)d_in[3];      // f32 [2]
    float*       out = (float*)d_out;              // f32 [128, 2]

    dim3 grid(SPLIT, BATCH);                       // 640 CTAs (R12-best wave)
    fused_kernel<<<grid, THREADS>>>(t32, emb, W, bia, out);
}